// round 13
// baseline (speedup 1.0000x reference)
#include <cuda_runtime.h>
#include <math.h>

// ---------------------------------------------------------------------------
// ParallelHeadNet: N_INP=128, N_HID=512, N_OUT=256, N_HEADS=64, N_SM=4
// Inputs (metadata order):
//  0: x          (128,128)        f32
//  1: last_out_sm(256,64)         f32
//  2: qw         (64,128)         f32
//  3: w1         (64,512,128)     f32
//  4: gn1_g      (64,512)         f32
//  5: gn1_b      (64,512)         f32
//  6: w2         (4,64,256,512)   f32
//  7: gn2_g      (4,64,256)       f32
//  8: gn2_b      (4,64,256)       f32
//  9: ws         (64,256,256)     f32
// 10: woo        (64,512)         f32
// Output: concat of two (256,64) f32 arrays (row-major) -> 32768 floats.
//
// Launch structure (dependency-aware, overlap-aware):
//   k1 (129 blocks x 1024 thr):
//        [0,64):   w1 branch -> g_h1
//        [64,128): ws row sums -> g_scalar  (independent; rides idle SMs)
//        128:      last_prod -> g_lp
//   k2 (256 blocks x 512 thr): w2 GEMV+GN+softmax -> g_part (dominant stream)
//   k3 (64 blocks):  gate + outputs
//
// L2 residency plan (126 MB L2, ~168 MB total weights):
//   default-cached (resident across graph replays): w1 16.8 + ws 16.8 +
//     w2[s<2] 67 MB  ->  ~101 MB resident set
//   evict-first (__ldcs): w2[s>=2] 67 MB -> steady-state DRAM traffic ~67 MB
//   Moves the binding ceiling from DRAM (~8 TB/s) toward LTS (~11.3 TB/s).
// ---------------------------------------------------------------------------

#define N_INP   128
#define N_HID   512
#define N_OUT   256
#define N_HEADS 64
#define N_SM    4
#define EPS_GN  1e-5f
#define TINY    1e-14f

// scratch (device globals: no allocation allowed)
__device__ float g_h1[N_HEADS * N_HID];              // 64*512
__device__ float g_part[N_SM * N_HEADS * N_OUT];     // per-s softmax, deterministic sum later
__device__ float g_scalar[N_HEADS * N_OUT];          // ws row sums, [h][o]
__device__ float g_lp[N_OUT];                        // prod_j last_out_sm[o,j]

__device__ __forceinline__ float warpSum(float v) {
#pragma unroll
    for (int o = 16; o; o >>= 1) v += __shfl_xor_sync(0xffffffffu, v, o);
    return v;
}
__device__ __forceinline__ float warpMax(float v) {
#pragma unroll
    for (int o = 16; o; o >>= 1) v = fmaxf(v, __shfl_xor_sync(0xffffffffu, v, o));
    return v;
}
__device__ __forceinline__ float warpProd(float v) {
#pragma unroll
    for (int o = 16; o; o >>= 1) v *= __shfl_xor_sync(0xffffffffu, v, o);
    return v;
}

__device__ __forceinline__ float4 ldcs4(const float4* p) {
#if __CUDA_ARCH__ >= 800
    return __ldcs(p);
#else
    return *p;
#endif
}

// ---------------------------------------------------------------------------
// k1: fused phase 1.
//  blocks [0,64):   head h: sub = qw_h.x^T ; z1 = w1_h@sub ; GN(512); softplus
//  blocks [64,128): head h-64: scalar[h,o] = sum_j ws[h,o,j]
//  block  128:      g_lp[o] = prod_j last[o,j]
//  block 1024 threads (32 warps)
// ---------------------------------------------------------------------------
__global__ __launch_bounds__(1024) void k1(
    const float* __restrict__ x, const float* __restrict__ qw,
    const float* __restrict__ w1,
    const float* __restrict__ gn1g, const float* __restrict__ gn1b,
    const float* __restrict__ ws, const float* __restrict__ last)
{
    const int tid = threadIdx.x, lane = tid & 31, wid = tid >> 5;

    if (blockIdx.x == 2 * N_HEADS) {
        // ---- last_prod: warp per row (8 rows/warp), coalesced ----
        for (int o = wid; o < N_OUT; o += 32) {
            float a = __ldg(last + o * N_HEADS + lane) *
                      __ldg(last + o * N_HEADS + lane + 32);
            a = warpProd(a);
            if (lane == 0) g_lp[o] = a;
        }
        return;
    }

    if (blockIdx.x >= N_HEADS) {
        // ---- ws row sums: one head per block, 32 warps x 8 rows ----
        const int h = blockIdx.x - N_HEADS;
        for (int o = wid; o < N_OUT; o += 32) {
            const float4* wr = (const float4*)(ws + ((size_t)h * N_OUT + o) * N_OUT);
            float a = 0.f;
#pragma unroll
            for (int k = 0; k < 2; k++) {
                float4 v = wr[lane + 32 * k];
                a += v.x + v.y + v.z + v.w;
            }
            a = warpSum(a);
            if (lane == 0) g_scalar[h * N_OUT + o] = a;
        }
        return;
    }

    // ---- w1 branch ----
    const int h = blockIdx.x;

    __shared__ float4 qwv[N_INP / 4];        // 128 floats
    __shared__ float  sub[N_INP];
    __shared__ float  zb[N_HID];
    __shared__ float  red1[16], red2[16];

    if (tid < N_INP / 4) qwv[tid] = ((const float4*)(qw + h * N_INP))[tid];
    __syncthreads();

    // sub[r] = sum_c x[r,c]*qw[h,c]  — warp per row, 4 rows/warp, coalesced
    for (int r = wid; r < N_INP; r += 32) {
        const float4* xr = (const float4*)(x + (size_t)r * N_INP);
        float4 xv = xr[lane];
        float4 qv = qwv[lane];
        float a = xv.x * qv.x + xv.y * qv.y + xv.z * qv.z + xv.w * qv.w;
        a = warpSum(a);
        if (lane == 0) sub[r] = a;
    }
    __syncthreads();

    // z1[o] = w1[h,o,:] . sub — 32 warps, 2 rows per iteration (MLP 2/lane)
    const float4* subv = (const float4*)sub;
    {
        float4 sv = subv[lane];
#pragma unroll
        for (int j = 0; j < 8; j++) {
            int o0 = wid + 64 * j;       // rows o0 and o0+32
            const float4* wr0 = (const float4*)(w1 + ((size_t)h * N_HID + o0) * N_INP);
            const float4* wr1 = (const float4*)(w1 + ((size_t)h * N_HID + o0 + 32) * N_INP);
            float4 w0 = wr0[lane];
            float4 w1v = wr1[lane];
            float a0 = w0.x * sv.x + w0.y * sv.y + w0.z * sv.z + w0.w * sv.w;
            float a1 = w1v.x * sv.x + w1v.y * sv.y + w1v.z * sv.z + w1v.w * sv.w;
            a0 = warpSum(a0);
            a1 = warpSum(a1);
            if (lane == 0) { zb[o0] = a0; zb[o0 + 32] = a1; }
        }
    }
    __syncthreads();

    // GroupNorm over 512 + softplus (warps 0-15 carry the data; all sync)
    const bool act = tid < N_HID;
    float z = act ? zb[tid] : 0.f;
    float s1 = warpSum(z);
    float s2 = warpSum(z * z);
    if (act && lane == 0) { red1[wid] = s1; red2[wid] = s2; }
    __syncthreads();
    if (wid == 0) {
        float a = (lane < 16) ? red1[lane] : 0.f;
        float b = (lane < 16) ? red2[lane] : 0.f;
        a = warpSum(a); b = warpSum(b);
        if (lane == 0) { red1[0] = a; red2[0] = b; }
    }
    __syncthreads();
    if (act) {
        float mu  = red1[0] * (1.f / N_HID);
        float var = red2[0] * (1.f / N_HID) - mu * mu;
        float rs  = rsqrtf(var + EPS_GN);
        float y   = (z - mu) * rs * gn1g[h * N_HID + tid] + gn1b[h * N_HID + tid];
        // stable softplus
        float sp = fmaxf(y, 0.f) + log1pf(expf(-fabsf(y)));
        g_h1[h * N_HID + tid] = sp;
    }
}

// ---------------------------------------------------------------------------
// k2: per (s,h): z = w2[s,h] @ h1[h] ; GN(256) ; softmax(256) -> g_part
// grid 256 (s*64+h), block 512.  Dominant HBM stream.
// s<2 half of w2 is default-cached (L2-resident across replays);
// s>=2 half is evict-first.
// ---------------------------------------------------------------------------
__global__ __launch_bounds__(512) void k2(
    const float* __restrict__ w2,
    const float* __restrict__ g2, const float* __restrict__ b2)
{
    const int b = blockIdx.x;
    const int s = b >> 6, h = b & 63;
    const int tid = threadIdx.x, lane = tid & 31, wid = tid >> 5;
    const bool streaming = (s >= 2);     // uniform per block

    __shared__ float4 h1v[N_HID / 4];        // 512 floats
    __shared__ float  zb[N_OUT];
    __shared__ float  red1[16], red2[16];

    // prefetch GN affine params early (overlap with GEMV weight stream)
    const bool act = tid < N_OUT;
    float gam = 0.f, bet = 0.f;
    if (act) {
        int idx = ((s * N_HEADS + h) * N_OUT) + tid;
        gam = __ldg(g2 + idx);
        bet = __ldg(b2 + idx);
    }

    if (tid < N_HID / 4) h1v[tid] = ((const float4*)(g_h1 + h * N_HID))[tid];
    __syncthreads();

    const float* wbase = w2 + (((size_t)s * N_HEADS + h) * N_OUT) * N_HID;

    // 16 warps, 256 rows -> 16 rows/warp; 2 rows per iteration => MLP=8
    if (streaming) {
#pragma unroll
        for (int j = 0; j < 8; j++) {
            int o0 = wid + 32 * j;           // rows o0 and o0+16
            const float4* wr0 = (const float4*)(wbase + (size_t)o0 * N_HID);
            const float4* wr1 = (const float4*)(wbase + (size_t)(o0 + 16) * N_HID);
            float a0 = 0.f, a1 = 0.f;
#pragma unroll
            for (int k = 0; k < 4; k++) {
                float4 w0 = ldcs4(wr0 + lane + 32 * k);
                float4 w1v = ldcs4(wr1 + lane + 32 * k);
                float4 hv = h1v[lane + 32 * k];
                a0 += w0.x * hv.x + w0.y * hv.y + w0.z * hv.z + w0.w * hv.w;
                a1 += w1v.x * hv.x + w1v.y * hv.y + w1v.z * hv.z + w1v.w * hv.w;
            }
            a0 = warpSum(a0);
            a1 = warpSum(a1);
            if (lane == 0) { zb[o0] = a0; zb[o0 + 16] = a1; }
        }
    } else {
#pragma unroll
        for (int j = 0; j < 8; j++) {
            int o0 = wid + 32 * j;
            const float4* wr0 = (const float4*)(wbase + (size_t)o0 * N_HID);
            const float4* wr1 = (const float4*)(wbase + (size_t)(o0 + 16) * N_HID);
            float a0 = 0.f, a1 = 0.f;
#pragma unroll
            for (int k = 0; k < 4; k++) {
                float4 w0 = wr0[lane + 32 * k];
                float4 w1v = wr1[lane + 32 * k];
                float4 hv = h1v[lane + 32 * k];
                a0 += w0.x * hv.x + w0.y * hv.y + w0.z * hv.z + w0.w * hv.w;
                a1 += w1v.x * hv.x + w1v.y * hv.y + w1v.z * hv.z + w1v.w * hv.w;
            }
            a0 = warpSum(a0);
            a1 = warpSum(a1);
            if (lane == 0) { zb[o0] = a0; zb[o0 + 16] = a1; }
        }
    }
    __syncthreads();

    float z = act ? zb[tid] : 0.f;
    float s1 = warpSum(z);
    float s2 = warpSum(z * z);
    if (lane == 0) { red1[wid] = s1; red2[wid] = s2; }
    __syncthreads();
    if (wid == 0) {
        float a = (lane < 16) ? red1[lane] : 0.f;
        float bb = (lane < 16) ? red2[lane] : 0.f;
        a = warpSum(a); bb = warpSum(bb);
        if (lane == 0) { red1[0] = a; red2[0] = bb; }
    }
    __syncthreads();
    float mu  = red1[0] * (1.f / N_OUT);
    float var = red2[0] * (1.f / N_OUT) - mu * mu;
    float rs  = rsqrtf(var + EPS_GN);

    float y = act ? ((z - mu) * rs * gam + bet) : -INFINITY;
    __syncthreads();   // protect red1 reuse

    // softmax over 256 (stable)
    float m = warpMax(y);
    if (lane == 0) red1[wid] = m;
    __syncthreads();
    if (wid == 0) {
        float a = (lane < 16) ? red1[lane] : -INFINITY;
        a = warpMax(a);
        if (lane == 0) red1[0] = a;
    }
    __syncthreads();
    float mx = red1[0];
    float e = act ? expf(y - mx) : 0.f;
    __syncthreads();   // protect red2 reuse
    float es = warpSum(e);
    if (lane == 0) red2[wid] = es;
    __syncthreads();
    if (wid == 0) {
        float a = (lane < 16) ? red2[lane] : 0.f;
        a = warpSum(a);
        if (lane == 0) red2[0] = a;
    }
    __syncthreads();
    if (act)
        g_part[(size_t)s * (N_HEADS * N_OUT) + h * N_OUT + tid] = e / red2[0];
}

// ---------------------------------------------------------------------------
// k3: out_sm, gate, outputs.  grid 64 (head), block 256 (o)
// ---------------------------------------------------------------------------
__global__ __launch_bounds__(256) void k3(
    const float* __restrict__ woo,
    float* __restrict__ out)
{
    const int h = blockIdx.x;
    const int o = threadIdx.x;
    const int lane = o & 31, wid = o >> 5;
    __shared__ float red1[8];

    float lp = g_lp[o];

    // out_sm[o,h] = sum_s softmax parts (deterministic fixed-order sum)
    float osm = g_part[h * N_OUT + o]
              + g_part[1 * (N_HEADS * N_OUT) + h * N_OUT + o]
              + g_part[2 * (N_HEADS * N_OUT) + h * N_OUT + o]
              + g_part[3 * (N_HEADS * N_OUT) + h * N_OUT + o];

    float term = __ldg(woo + h * 2 * N_OUT + o) * lp
               + __ldg(woo + h * 2 * N_OUT + N_OUT + o) * osm;
    float t = warpSum(term);
    if (lane == 0) red1[wid] = t;
    __syncthreads();
    if (wid == 0) {
        float a = (lane < 8) ? red1[lane] : 0.f;
        a = warpSum(a);
        if (lane == 0) red1[0] = a;
    }
    __syncthreads();
    float logit = red1[0];
    float onoff = 1.f / (1.f + expf(-logit));

    float v = onoff * osm;
    out[o * N_HEADS + h] = fmaxf(v, TINY);
    float sc = v * g_scalar[h * N_OUT + o];
    out[N_OUT * N_HEADS + o * N_HEADS + h] = (fabsf(sc) <= TINY) ? TINY : sc;
}

// ---------------------------------------------------------------------------

extern "C" void kernel_launch(void* const* d_in, const int* in_sizes, int n_in,
                              void* d_out, int out_size)
{
    const float* x    = (const float*)d_in[0];
    const float* last = (const float*)d_in[1];
    const float* qw   = (const float*)d_in[2];
    const float* w1   = (const float*)d_in[3];
    const float* gn1g = (const float*)d_in[4];
    const float* gn1b = (const float*)d_in[5];
    const float* w2   = (const float*)d_in[6];
    const float* gn2g = (const float*)d_in[7];
    const float* gn2b = (const float*)d_in[8];
    const float* ws   = (const float*)d_in[9];
    const float* woo  = (const float*)d_in[10];
    float* out = (float*)d_out;

    k1<<<2 * N_HEADS + 1, 1024>>>(x, qw, w1, gn1g, gn1b, ws, last);
    k2<<<N_SM * N_HEADS, 512>>>(w2, gn2g, gn2b);
    k3<<<N_HEADS, 256>>>(woo, out);
}

// round 16
// speedup vs baseline: 1.0607x; 1.0607x over previous
#include <cuda_runtime.h>
#include <math.h>

// ---------------------------------------------------------------------------
// ParallelHeadNet: N_INP=128, N_HID=512, N_OUT=256, N_HEADS=64, N_SM=4
// R13 post-mortem fix (awaiting measurement): GEMV loops were latency-bound
// (k1: 33% DRAM, issue 20%) because warpSum shuffle chains sat inside the
// load loop. Now: batch all loads per warp into acc[16], reduce once at end.
// ---------------------------------------------------------------------------

#define N_INP   128
#define N_HID   512
#define N_OUT   256
#define N_HEADS 64
#define N_SM    4
#define EPS_GN  1e-5f
#define TINY    1e-14f

__device__ float g_h1[N_HEADS * N_HID];
__device__ float g_part[N_SM * N_HEADS * N_OUT];
__device__ float g_scalar[N_HEADS * N_OUT];
__device__ float g_lp[N_OUT];

__device__ __forceinline__ float warpSum(float v) {
#pragma unroll
    for (int o = 16; o; o >>= 1) v += __shfl_xor_sync(0xffffffffu, v, o);
    return v;
}
__device__ __forceinline__ float warpMax(float v) {
#pragma unroll
    for (int o = 16; o; o >>= 1) v = fmaxf(v, __shfl_xor_sync(0xffffffffu, v, o));
    return v;
}
__device__ __forceinline__ float warpProd(float v) {
#pragma unroll
    for (int o = 16; o; o >>= 1) v *= __shfl_xor_sync(0xffffffffu, v, o);
    return v;
}
__device__ __forceinline__ float4 ldcs4(const float4* p) {
#if __CUDA_ARCH__ >= 800
    return __ldcs(p);
#else
    return *p;
#endif
}
__device__ __forceinline__ float dot4(float4 a, float4 b) {
    return a.x * b.x + a.y * b.y + a.z * b.z + a.w * b.w;
}

// ---------------------------------------------------------------------------
// k1: fused phase 1 (129 blocks x 1024 thr)
//  [0,64):   head h: sub = qw_h.x^T ; z1 = w1_h@sub ; GN(512); softplus
//  [64,128): head h-64: scalar[h,o] = sum_j ws[h,o,j]
//  128:      g_lp[o] = prod_j last[o,j]
// ---------------------------------------------------------------------------
__global__ __launch_bounds__(1024, 1) void k1(
    const float* __restrict__ x, const float* __restrict__ qw,
    const float* __restrict__ w1,
    const float* __restrict__ gn1g, const float* __restrict__ gn1b,
    const float* __restrict__ ws, const float* __restrict__ last)
{
    const int tid = threadIdx.x, lane = tid & 31, wid = tid >> 5;

    if (blockIdx.x == 2 * N_HEADS) {
        // ---- last_prod: warp per row (8 rows/warp), coalesced ----
        for (int o = wid; o < N_OUT; o += 32) {
            float a = __ldg(last + o * N_HEADS + lane) *
                      __ldg(last + o * N_HEADS + lane + 32);
            a = warpProd(a);
            if (lane == 0) g_lp[o] = a;
        }
        return;
    }

    if (blockIdx.x >= N_HEADS) {
        // ---- ws row sums: one head per block, 8 rows/warp, batched loads ----
        const int h = blockIdx.x - N_HEADS;
        const int base_o = wid * 8;
        float acc[8];
#pragma unroll
        for (int r = 0; r < 8; r++) {
            const float4* wr = (const float4*)(ws + ((size_t)h * N_OUT + base_o + r) * N_OUT);
            float4 v0 = wr[lane];
            float4 v1 = wr[lane + 32];
            acc[r] = (v0.x + v0.y + v0.z + v0.w) + (v1.x + v1.y + v1.z + v1.w);
        }
#pragma unroll
        for (int r = 0; r < 8; r++) {
            float a = warpSum(acc[r]);
            if (lane == 0) g_scalar[h * N_OUT + base_o + r] = a;
        }
        return;
    }

    // ---- w1 branch ----
    const int h = blockIdx.x;

    __shared__ float4 qwv[N_INP / 4];
    __shared__ float  sub[N_INP];
    __shared__ float  zb[N_HID];
    __shared__ float  red1[16], red2[16];

    if (tid < N_INP / 4) qwv[tid] = ((const float4*)(qw + h * N_INP))[tid];
    __syncthreads();

    // sub[r] = sum_c x[r,c]*qw[h,c] — 4 rows/warp, batched then reduced
    {
        float4 qv = qwv[lane];
        float accs[4];
#pragma unroll
        for (int r4 = 0; r4 < 4; r4++) {
            int r = wid + 32 * r4;
            const float4* xr = (const float4*)(x + (size_t)r * N_INP);
            accs[r4] = dot4(xr[lane], qv);
        }
#pragma unroll
        for (int r4 = 0; r4 < 4; r4++) {
            float a = warpSum(accs[r4]);
            if (lane == 0) sub[wid + 32 * r4] = a;
        }
    }
    __syncthreads();

    // z1: 16 rows per warp; ALL 16 loads batched, reductions deferred
    {
        float4 sv = ((const float4*)sub)[lane];
        const int base_o = wid * 16;
        float acc[16];
#pragma unroll
        for (int r = 0; r < 16; r++) {
            const float4* wr = (const float4*)(w1 + ((size_t)h * N_HID + base_o + r) * N_INP);
            acc[r] = dot4(wr[lane], sv);
        }
#pragma unroll
        for (int r = 0; r < 16; r++) {
            float a = warpSum(acc[r]);
            if (lane == 0) zb[base_o + r] = a;
        }
    }
    __syncthreads();

    // GroupNorm over 512 + softplus (warps 0-15 carry data; all sync)
    const bool act = tid < N_HID;
    float z = act ? zb[tid] : 0.f;
    float s1 = warpSum(z);
    float s2 = warpSum(z * z);
    if (act && lane == 0) { red1[wid] = s1; red2[wid] = s2; }
    __syncthreads();
    if (wid == 0) {
        float a = (lane < 16) ? red1[lane] : 0.f;
        float b = (lane < 16) ? red2[lane] : 0.f;
        a = warpSum(a); b = warpSum(b);
        if (lane == 0) { red1[0] = a; red2[0] = b; }
    }
    __syncthreads();
    if (act) {
        float mu  = red1[0] * (1.f / N_HID);
        float var = red2[0] * (1.f / N_HID) - mu * mu;
        float rs  = rsqrtf(var + EPS_GN);
        float y   = (z - mu) * rs * gn1g[h * N_HID + tid] + gn1b[h * N_HID + tid];
        float sp = fmaxf(y, 0.f) + log1pf(expf(-fabsf(y)));
        g_h1[h * N_HID + tid] = sp;
    }
}

// ---------------------------------------------------------------------------
// k2: per (s,h): z = w2[s,h] @ h1[h] ; GN(256) ; softmax(256) -> g_part
// grid 256, block 512, 2 CTAs/SM (reg-capped). 16 rows/warp, loads batched.
// s<2 half of w2 default-cached (L2-resident); s>=2 evict-first.
// ---------------------------------------------------------------------------
__global__ __launch_bounds__(512, 2) void k2(
    const float* __restrict__ w2,
    const float* __restrict__ g2, const float* __restrict__ b2)
{
    const int b = blockIdx.x;
    const int s = b >> 6, h = b & 63;
    const int tid = threadIdx.x, lane = tid & 31, wid = tid >> 5;
    const bool streaming = (s >= 2);     // uniform per block

    __shared__ float4 h1v[N_HID / 4];
    __shared__ float  zb[N_OUT];
    __shared__ float  red1[16], red2[16];

    const bool act = tid < N_OUT;
    float gam = 0.f, bet = 0.f;
    if (act) {
        int idx = ((s * N_HEADS + h) * N_OUT) + tid;
        gam = __ldg(g2 + idx);
        bet = __ldg(b2 + idx);
    }

    if (tid < N_HID / 4) h1v[tid] = ((const float4*)(g_h1 + h * N_HID))[tid];
    __syncthreads();

    // hoist the shared operand into registers (same 4 float4 for every row)
    float4 hv0 = h1v[lane];
    float4 hv1 = h1v[lane + 32];
    float4 hv2 = h1v[lane + 64];
    float4 hv3 = h1v[lane + 96];

    const float* wbase = w2 + (((size_t)s * N_HEADS + h) * N_OUT) * N_HID;
    const int base_o = wid * 16;

    float acc[16];
    if (streaming) {
#pragma unroll
        for (int r = 0; r < 16; r++) {
            const float4* wr = (const float4*)(wbase + (size_t)(base_o + r) * N_HID);
            float a = dot4(ldcs4(wr + lane), hv0);
            a += dot4(ldcs4(wr + lane + 32), hv1);
            a += dot4(ldcs4(wr + lane + 64), hv2);
            a += dot4(ldcs4(wr + lane + 96), hv3);
            acc[r] = a;
        }
    } else {
#pragma unroll
        for (int r = 0; r < 16; r++) {
            const float4* wr = (const float4*)(wbase + (size_t)(base_o + r) * N_HID);
            float a = dot4(wr[lane], hv0);
            a += dot4(wr[lane + 32], hv1);
            a += dot4(wr[lane + 64], hv2);
            a += dot4(wr[lane + 96], hv3);
            acc[r] = a;
        }
    }
    // deferred reductions: 16 independent shuffle trees, pipelined
#pragma unroll
    for (int r = 0; r < 16; r++) {
        float a = warpSum(acc[r]);
        if (lane == 0) zb[base_o + r] = a;
    }
    __syncthreads();

    float z = act ? zb[tid] : 0.f;
    float s1 = warpSum(z);
    float s2 = warpSum(z * z);
    if (lane == 0) { red1[wid] = s1; red2[wid] = s2; }
    __syncthreads();
    if (wid == 0) {
        float a = (lane < 16) ? red1[lane] : 0.f;
        float bb = (lane < 16) ? red2[lane] : 0.f;
        a = warpSum(a); bb = warpSum(bb);
        if (lane == 0) { red1[0] = a; red2[0] = bb; }
    }
    __syncthreads();
    float mu  = red1[0] * (1.f / N_OUT);
    float var = red2[0] * (1.f / N_OUT) - mu * mu;
    float rs  = rsqrtf(var + EPS_GN);

    float y = act ? ((z - mu) * rs * gam + bet) : -INFINITY;
    __syncthreads();   // protect red1 reuse

    // softmax over 256 (stable)
    float m = warpMax(y);
    if (lane == 0) red1[wid] = m;
    __syncthreads();
    if (wid == 0) {
        float a = (lane < 16) ? red1[lane] : -INFINITY;
        a = warpMax(a);
        if (lane == 0) red1[0] = a;
    }
    __syncthreads();
    float mx = red1[0];
    float e = act ? expf(y - mx) : 0.f;
    __syncthreads();   // protect red2 reuse
    float es = warpSum(e);
    if (lane == 0) red2[wid] = es;
    __syncthreads();
    if (wid == 0) {
        float a = (lane < 16) ? red2[lane] : 0.f;
        a = warpSum(a);
        if (lane == 0) red2[0] = a;
    }
    __syncthreads();
    if (act)
        g_part[(size_t)s * (N_HEADS * N_OUT) + h * N_OUT + tid] = e / red2[0];
}

// ---------------------------------------------------------------------------
// k3: out_sm, gate, outputs.  grid 64 (head), block 256 (o)
// ---------------------------------------------------------------------------
__global__ __launch_bounds__(256) void k3(
    const float* __restrict__ woo,
    float* __restrict__ out)
{
    const int h = blockIdx.x;
    const int o = threadIdx.x;
    const int lane = o & 31, wid = o >> 5;
    __shared__ float red1[8];

    float lp = g_lp[o];

    float osm = g_part[h * N_OUT + o]
              + g_part[1 * (N_HEADS * N_OUT) + h * N_OUT + o]
              + g_part[2 * (N_HEADS * N_OUT) + h * N_OUT + o]
              + g_part[3 * (N_HEADS * N_OUT) + h * N_OUT + o];

    float term = __ldg(woo + h * 2 * N_OUT + o) * lp
               + __ldg(woo + h * 2 * N_OUT + N_OUT + o) * osm;
    float t = warpSum(term);
    if (lane == 0) red1[wid] = t;
    __syncthreads();
    if (wid == 0) {
        float a = (lane < 8) ? red1[lane] : 0.f;
        a = warpSum(a);
        if (lane == 0) red1[0] = a;
    }
    __syncthreads();
    float logit = red1[0];
    float onoff = 1.f / (1.f + expf(-logit));

    float v = onoff * osm;
    out[o * N_HEADS + h] = fmaxf(v, TINY);
    float sc = v * g_scalar[h * N_OUT + o];
    out[N_OUT * N_HEADS + o * N_HEADS + h] = (fabsf(sc) <= TINY) ? TINY : sc;
}

// ---------------------------------------------------------------------------

extern "C" void kernel_launch(void* const* d_in, const int* in_sizes, int n_in,
                              void* d_out, int out_size)
{
    const float* x    = (const float*)d_in[0];
    const float* last = (const float*)d_in[1];
    const float* qw   = (const float*)d_in[2];
    const float* w1   = (const float*)d_in[3];
    const float* gn1g = (const float*)d_in[4];
    const float* gn1b = (const float*)d_in[5];
    const float* w2   = (const float*)d_in[6];
    const float* gn2g = (const float*)d_in[7];
    const float* gn2b = (const float*)d_in[8];
    const float* ws   = (const float*)d_in[9];
    const float* woo  = (const float*)d_in[10];
    float* out = (float*)d_out;

    k1<<<2 * N_HEADS + 1, 1024>>>(x, qw, w1, gn1g, gn1b, ws, last);
    k2<<<N_SM * N_HEADS, 512>>>(w2, gn2g, gn2b);
    k3<<<N_HEADS, 256>>>(woo, out);
}